// round 4
// baseline (speedup 1.0000x reference)
#include <cuda_runtime.h>

// RNNBlock: out = relu( RNN_backwards(x; w_in, w_rec, b_rnn) @ w_d + b_d )
// fp32 throughout, packed f32x2 FMA path (2x fp32 rate on Blackwell).

typedef unsigned long long u64;

#define B_TOT    32768
#define T_STEPS  79
#define F_IN     16
#define C_DIM    256
#define BM       128      // batch rows per CTA
#define NTHREADS 512      // 16 warps; each warp owns 8 batch rows

#define SMEM_FLOATS (BM*C_DIM + 32*C_DIM + F_IN*C_DIM)   // h + w_chunk + w_in
#define SMEM_BYTES  (SMEM_FLOATS * 4)                     // 176 KB

__device__ __forceinline__ u64 pack2(float lo, float hi) {
    u64 r; asm("mov.b64 %0, {%1, %2};" : "=l"(r) : "f"(lo), "f"(hi)); return r;
}
__device__ __forceinline__ u64 dup2(float v) {
    u64 r; asm("mov.b64 %0, {%1, %1};" : "=l"(r) : "f"(v)); return r;
}
__device__ __forceinline__ void unpack2(u64 v, float& lo, float& hi) {
    asm("mov.b64 {%0, %1}, %2;" : "=f"(lo), "=f"(hi) : "l"(v));
}
__device__ __forceinline__ void fma2(u64& d, u64 a, u64 b) {
    asm("fma.rn.f32x2 %0, %1, %2, %0;" : "+l"(d) : "l"(a), "l"(b));
}

// acc[b][p] += h[bloc+b][k] * W[k][c0+2p .. c0+2p+1]  for all k in 0..255,
// with W streamed from global in 32-row (32 KB) SMEM chunks, next chunk
// register-prefetched so the LDG latency overlaps compute.
__device__ __forceinline__ void mm256(
    const float* __restrict__ wglob,
    float* __restrict__ w_sm,
    const float* __restrict__ hbase,      // h_sm + bloc*C_DIM
    int c0, int tid, u64 acc[8][4])
{
    float4 pf0, pf1, pf2, pf3;
    {
        const float4* src = (const float4*)wglob;
        pf0 = src[tid];               pf1 = src[tid + NTHREADS];
        pf2 = src[tid + 2*NTHREADS];  pf3 = src[tid + 3*NTHREADS];
    }
    #pragma unroll 1
    for (int kc = 0; kc < 8; ++kc) {
        __syncthreads();                      // previous chunk fully consumed
        {
            float4* dst = (float4*)w_sm;
            dst[tid]               = pf0;
            dst[tid + NTHREADS]    = pf1;
            dst[tid + 2*NTHREADS]  = pf2;
            dst[tid + 3*NTHREADS]  = pf3;
        }
        if (kc < 7) {                          // prefetch next chunk
            const float4* src = (const float4*)(wglob + (kc + 1) * 32 * C_DIM);
            pf0 = src[tid];               pf1 = src[tid + NTHREADS];
            pf2 = src[tid + 2*NTHREADS];  pf3 = src[tid + 3*NTHREADS];
        }
        __syncthreads();                      // chunk visible
        const float* hk = hbase + kc * 32;
        #pragma unroll 2
        for (int kk = 0; kk < 32; ++kk) {
            const u64* wrow = (const u64*)(w_sm + kk * C_DIM + c0);
            u64 wp0 = wrow[0], wp1 = wrow[1], wp2 = wrow[2], wp3 = wrow[3];
            #pragma unroll
            for (int b = 0; b < 8; ++b) {
                u64 hd = dup2(hk[b * C_DIM + kk]);   // warp-broadcast LDS
                fma2(acc[b][0], hd, wp0);
                fma2(acc[b][1], hd, wp1);
                fma2(acc[b][2], hd, wp2);
                fma2(acc[b][3], hd, wp3);
            }
        }
    }
}

__global__ void __launch_bounds__(NTHREADS, 1)
rnn_fused(const float* __restrict__ x,     const float* __restrict__ w_in,
          const float* __restrict__ w_rec, const float* __restrict__ b_rnn,
          const float* __restrict__ w_d,   const float* __restrict__ b_d,
          float* __restrict__ out)
{
    extern __shared__ float smem[];
    float* h_sm  = smem;                    // BM  x 256  (128 KB)
    float* w_sm  = smem + BM * C_DIM;       // 32  x 256  (32 KB)  weight chunk
    float* wi_sm = w_sm + 32 * C_DIM;       // 16  x 256  (16 KB)  w_in

    const int tid  = threadIdx.x;
    const int lane = tid & 31;
    const int wid  = tid >> 5;
    const int c0   = lane << 3;             // 8 columns per lane (4 f32x2 pairs)
    const int bloc = wid  << 3;             // 8 batch rows per warp
    const long bglob = (long)blockIdx.x * BM + bloc;

    // stage w_in once
    {
        const float4* src = (const float4*)w_in;
        float4* dst = (float4*)wi_sm;
        for (int i = tid; i < (F_IN * C_DIM) / 4; i += NTHREADS) dst[i] = src[i];
    }
    u64 bp[4];
    #pragma unroll
    for (int p = 0; p < 4; ++p)
        bp[p] = pack2(b_rnn[c0 + 2*p], b_rnn[c0 + 2*p + 1]);
    __syncthreads();

    u64 acc[8][4];
    const float* hbase = h_sm + bloc * C_DIM;

    for (int s = 0; s < T_STEPS; ++s) {
        const int t = T_STEPS - 1 - s;      // go_backwards

        // ---- init acc = b_rnn + x[:,t,:] @ w_in  (warp-local, shfl bcast) ----
        float xr0, xr1, xr2, xr3;
        {
            const int r = lane >> 2, q = lane & 3;   // lane holds quad q of row r
            const float4 xq = *(const float4*)(x + ((bglob + r) * T_STEPS + t) * F_IN + q * 4);
            xr0 = xq.x; xr1 = xq.y; xr2 = xq.z; xr3 = xq.w;
        }
        #pragma unroll
        for (int b = 0; b < 8; ++b)
            #pragma unroll
            for (int p = 0; p < 4; ++p) acc[b][p] = bp[p];

        #pragma unroll
        for (int f = 0; f < F_IN; ++f) {
            const u64* wrow = (const u64*)(wi_sm + f * C_DIM + c0);
            u64 wp0 = wrow[0], wp1 = wrow[1], wp2 = wrow[2], wp3 = wrow[3];
            float xsel = ((f & 3) == 0) ? xr0 : ((f & 3) == 1) ? xr1
                       : ((f & 3) == 2) ? xr2 : xr3;            // const after unroll
            #pragma unroll
            for (int b = 0; b < 8; ++b) {
                float xv = __shfl_sync(0xffffffffu, xsel, (b << 2) | (f >> 2));
                u64 xd = dup2(xv);
                fma2(acc[b][0], xd, wp0);
                fma2(acc[b][1], xd, wp1);
                fma2(acc[b][2], xd, wp2);
                fma2(acc[b][3], xd, wp3);
            }
        }

        // ---- recurrent term: acc += h @ w_rec (skip at s=0: h==0) ----
        if (s > 0) mm256(w_rec, w_sm, hbase, c0, tid, acc);

        // ---- relu + writeback h (warp-private rows: no barrier needed) ----
        #pragma unroll
        for (int b = 0; b < 8; ++b)
            #pragma unroll
            for (int p = 0; p < 4; ++p) {
                float lo, hi; unpack2(acc[b][p], lo, hi);
                lo = fmaxf(lo, 0.f); hi = fmaxf(hi, 0.f);
                *(u64*)(h_sm + (bloc + b) * C_DIM + c0 + 2*p) = pack2(lo, hi);
            }
    }

    // ---- dense head: out = relu(h_last @ w_d + b_d) ----
    #pragma unroll
    for (int p = 0; p < 4; ++p)
        bp[p] = pack2(b_d[c0 + 2*p], b_d[c0 + 2*p + 1]);
    #pragma unroll
    for (int b = 0; b < 8; ++b)
        #pragma unroll
        for (int p = 0; p < 4; ++p) acc[b][p] = bp[p];

    mm256(w_d, w_sm, hbase, c0, tid, acc);

    #pragma unroll
    for (int b = 0; b < 8; ++b) {
        float* orow = out + (bglob + b) * C_DIM;
        #pragma unroll
        for (int p = 0; p < 4; ++p) {
            float lo, hi; unpack2(acc[b][p], lo, hi);
            float2 v = make_float2(fmaxf(lo, 0.f), fmaxf(hi, 0.f));
            *(float2*)(orow + c0 + 2*p) = v;
        }
    }
}

extern "C" void kernel_launch(void* const* d_in, const int* in_sizes, int n_in,
                              void* d_out, int out_size)
{
    const float* x     = (const float*)d_in[0];
    const float* w_in  = (const float*)d_in[1];
    const float* w_rec = (const float*)d_in[2];
    const float* b_rnn = (const float*)d_in[3];
    const float* w_d   = (const float*)d_in[4];
    const float* b_d   = (const float*)d_in[5];
    float* out = (float*)d_out;

    // idempotent; safe under graph capture (not a stream op)
    cudaFuncSetAttribute(rnn_fused, cudaFuncAttributeMaxDynamicSharedMemorySize, SMEM_BYTES);

    rnn_fused<<<B_TOT / BM, NTHREADS, SMEM_BYTES>>>(x, w_in, w_rec, b_rnn, w_d, b_d, out);
}

// round 5
// speedup vs baseline: 1.2794x; 1.2794x over previous
#include <cuda_runtime.h>

// RNNBlock: out = relu( RNN_backwards(x; w_in, w_rec, b_rnn) @ w_d + b_d )
// fp32 exact, packed f32x2 FMA path. R5: conflict-free column interleave
// (col = 2*lane + 64*p), cp.async double-buffered w chunks, smem-staged x.

typedef unsigned long long u64;

#define B_TOT    32768
#define T_STEPS  79
#define F_IN     16
#define C_DIM    256
#define BM       128      // batch rows per CTA
#define NTHREADS 512      // 16 warps; each warp owns 8 batch rows
#define CHUNK    32       // w rows per smem chunk (32 KB)

// smem: h[128*256] | wbuf0[32*256] | wbuf1[32*256] | w_in[16*256] | xs[16*128]
#define SM_H     0
#define SM_W0    (BM * C_DIM)
#define SM_W1    (SM_W0 + CHUNK * C_DIM)
#define SM_WI    (SM_W1 + CHUNK * C_DIM)
#define SM_XS    (SM_WI + F_IN * C_DIM)
#define SMEM_FLOATS (SM_XS + NTHREADS / 32 * 8 * F_IN)
#define SMEM_BYTES  (SMEM_FLOATS * 4)          // 221184 B <= 227 KB

__device__ __forceinline__ u64 pack2(float lo, float hi) {
    u64 r; asm("mov.b64 %0, {%1, %2};" : "=l"(r) : "f"(lo), "f"(hi)); return r;
}
__device__ __forceinline__ u64 dup2(float v) {
    u64 r; asm("mov.b64 %0, {%1, %1};" : "=l"(r) : "f"(v)); return r;
}
__device__ __forceinline__ void unpack2(u64 v, float& lo, float& hi) {
    asm("mov.b64 {%0, %1}, %2;" : "=f"(lo), "=f"(hi) : "l"(v));
}
__device__ __forceinline__ void fma2(u64& d, u64 a, u64 b) {
    asm("fma.rn.f32x2 %0, %1, %2, %0;" : "+l"(d) : "l"(a), "l"(b));
}

__device__ __forceinline__ void cp16(float* dst, const float* src) {
    unsigned d = (unsigned)__cvta_generic_to_shared(dst);
    asm volatile("cp.async.cg.shared.global [%0], [%1], 16;" :: "r"(d), "l"(src));
}
__device__ __forceinline__ void cp_commit() {
    asm volatile("cp.async.commit_group;");
}
template <int N> __device__ __forceinline__ void cp_wait() {
    asm volatile("cp.async.wait_group %0;" :: "n"(N));
}

__device__ __forceinline__ void issue_chunk(const float* __restrict__ wglob,
                                            float* __restrict__ buf,
                                            int kc, int tid) {
    const float* src = wglob + kc * CHUNK * C_DIM;
    #pragma unroll
    for (int j = 0; j < 4; ++j)
        cp16(buf + (tid + j * NTHREADS) * 4, src + (tid + j * NTHREADS) * 4);
    cp_commit();
}

// acc[b][p] += h[bloc+b][k] * W[k][2*lane + 64*p (+1)]  for k in 0..255.
// W streamed from global in 32-row chunks, double-buffered via cp.async.
__device__ __forceinline__ void mm256(
    const float* __restrict__ wglob,
    float* __restrict__ wbuf0, float* __restrict__ wbuf1,
    const float* __restrict__ hbase,      // h_sm + bloc*C_DIM
    int c2, int tid, u64 acc[8][4])
{
    issue_chunk(wglob, wbuf0, 0, tid);
    issue_chunk(wglob, wbuf1, 1, tid);
    #pragma unroll 1
    for (int kc = 0; kc < 8; ++kc) {
        if (kc < 7) cp_wait<1>(); else cp_wait<0>();
        __syncthreads();                           // chunk kc visible everywhere
        const float* wc = (kc & 1) ? wbuf1 : wbuf0;
        const float* hk = hbase + kc * CHUNK;
        #pragma unroll 2
        for (int kk = 0; kk < CHUNK; ++kk) {
            const float* wr = wc + kk * C_DIM + c2;    // lane-contiguous: no conflicts
            u64 wp0 = *(const u64*)(wr);
            u64 wp1 = *(const u64*)(wr + 64);
            u64 wp2 = *(const u64*)(wr + 128);
            u64 wp3 = *(const u64*)(wr + 192);
            #pragma unroll
            for (int b = 0; b < 8; ++b) {
                u64 hd = dup2(hk[b * C_DIM + kk]);     // warp-broadcast LDS
                fma2(acc[b][0], hd, wp0);
                fma2(acc[b][1], hd, wp1);
                fma2(acc[b][2], hd, wp2);
                fma2(acc[b][3], hd, wp3);
            }
        }
        __syncthreads();                           // all warps done with this buffer
        if (kc + 2 < 8) issue_chunk(wglob, (kc & 1) ? wbuf1 : wbuf0, kc + 2, tid);
    }
}

__global__ void __launch_bounds__(NTHREADS, 1)
rnn_fused(const float* __restrict__ x,     const float* __restrict__ w_in,
          const float* __restrict__ w_rec, const float* __restrict__ b_rnn,
          const float* __restrict__ w_d,   const float* __restrict__ b_d,
          float* __restrict__ out)
{
    extern __shared__ float smem[];
    float* h_sm  = smem + SM_H;
    float* wbuf0 = smem + SM_W0;
    float* wbuf1 = smem + SM_W1;
    float* wi_sm = smem + SM_WI;

    const int tid  = threadIdx.x;
    const int lane = tid & 31;
    const int wid  = tid >> 5;
    const int c2   = lane << 1;             // base column; pairs at +0,+64,+128,+192
    const int bloc = wid  << 3;             // 8 batch rows per warp
    const long bglob = (long)blockIdx.x * BM + bloc;
    float* xs_w = smem + SM_XS + wid * (8 * F_IN);   // warp-private x stage

    // stage w_in once (plain row-major)
    {
        const float4* src = (const float4*)w_in;
        float4* dst = (float4*)wi_sm;
        for (int i = tid; i < (F_IN * C_DIM) / 4; i += NTHREADS) dst[i] = src[i];
    }
    u64 bp[4];
    #pragma unroll
    for (int p = 0; p < 4; ++p)
        bp[p] = pack2(b_rnn[c2 + 64*p], b_rnn[c2 + 64*p + 1]);
    __syncthreads();

    u64 acc[8][4];
    const float* hbase = h_sm + bloc * C_DIM;
    const int r = lane >> 2, q = lane & 3;  // x staging: lane holds quad q of row r

    for (int s = 0; s < T_STEPS; ++s) {
        const int t = T_STEPS - 1 - s;      // go_backwards

        // ---- stage x[:,t,:] for this warp's 8 rows (warp-private smem) ----
        __syncwarp();                       // prev step's reads done
        {
            const float4 xq = *(const float4*)(x + ((bglob + r) * T_STEPS + t) * F_IN + q * 4);
            *(float4*)(xs_w + r * F_IN + q * 4) = xq;
        }
        __syncwarp();

        // ---- acc = b_rnn + x_t @ w_in (same broadcast-LDS structure) ----
        #pragma unroll
        for (int b = 0; b < 8; ++b)
            #pragma unroll
            for (int p = 0; p < 4; ++p) acc[b][p] = bp[p];

        #pragma unroll 4
        for (int f = 0; f < F_IN; ++f) {
            const float* wr = wi_sm + f * C_DIM + c2;
            u64 wp0 = *(const u64*)(wr);
            u64 wp1 = *(const u64*)(wr + 64);
            u64 wp2 = *(const u64*)(wr + 128);
            u64 wp3 = *(const u64*)(wr + 192);
            #pragma unroll
            for (int b = 0; b < 8; ++b) {
                u64 xd = dup2(xs_w[b * F_IN + f]);
                fma2(acc[b][0], xd, wp0);
                fma2(acc[b][1], xd, wp1);
                fma2(acc[b][2], xd, wp2);
                fma2(acc[b][3], xd, wp3);
            }
        }

        // ---- recurrent term: acc += h @ w_rec (skip at s=0: h==0) ----
        if (s > 0) mm256(w_rec, wbuf0, wbuf1, hbase, c2, tid, acc);

        // ---- relu + writeback h (warp-private rows, lane-contiguous STS) ----
        #pragma unroll
        for (int b = 0; b < 8; ++b) {
            float* hrow = h_sm + (bloc + b) * C_DIM + c2;
            #pragma unroll
            for (int p = 0; p < 4; ++p) {
                float lo, hi; unpack2(acc[b][p], lo, hi);
                lo = fmaxf(lo, 0.f); hi = fmaxf(hi, 0.f);
                *(u64*)(hrow + 64*p) = pack2(lo, hi);
            }
        }
    }

    // ---- dense head: out = relu(h_last @ w_d + b_d) ----
    #pragma unroll
    for (int p = 0; p < 4; ++p)
        bp[p] = pack2(b_d[c2 + 64*p], b_d[c2 + 64*p + 1]);
    #pragma unroll
    for (int b = 0; b < 8; ++b)
        #pragma unroll
        for (int p = 0; p < 4; ++p) acc[b][p] = bp[p];

    mm256(w_d, wbuf0, wbuf1, hbase, c2, tid, acc);

    #pragma unroll
    for (int b = 0; b < 8; ++b) {
        float* orow = out + (bglob + b) * C_DIM + c2;
        #pragma unroll
        for (int p = 0; p < 4; ++p) {
            float lo, hi; unpack2(acc[b][p], lo, hi);
            float2 v = make_float2(fmaxf(lo, 0.f), fmaxf(hi, 0.f));
            *(float2*)(orow + 64*p) = v;
        }
    }
}

extern "C" void kernel_launch(void* const* d_in, const int* in_sizes, int n_in,
                              void* d_out, int out_size)
{
    const float* x     = (const float*)d_in[0];
    const float* w_in  = (const float*)d_in[1];
    const float* w_rec = (const float*)d_in[2];
    const float* b_rnn = (const float*)d_in[3];
    const float* w_d   = (const float*)d_in[4];
    const float* b_d   = (const float*)d_in[5];
    float* out = (float*)d_out;

    cudaFuncSetAttribute(rnn_fused, cudaFuncAttributeMaxDynamicSharedMemorySize, SMEM_BYTES);

    rnn_fused<<<B_TOT / BM, NTHREADS, SMEM_BYTES>>>(x, w_in, w_rec, b_rnn, w_d, b_d, out);
}